// round 5
// baseline (speedup 1.0000x reference)
#include <cuda_runtime.h>
#include <math.h>

#define E_DIM 256
#define F_DIM 768
#define B_DIM 256
#define TI    64
#define BSP   260
#define ATT_SCALE 0.0625f

#define SMEM_FLOATS (3*TI*E_DIM + 16*BSP + E_DIM + TI)
#define SMEM_BYTES  (SMEM_FLOATS * (int)sizeof(float))

typedef unsigned long long ull;

// packed fp32x2 helpers (FFMA2 path — ptxas never emits this from C++)
__device__ __forceinline__ ull dup2(float a) {
    ull r; asm("mov.b64 %0, {%1, %1};" : "=l"(r) : "f"(a)); return r;
}
__device__ __forceinline__ void ffma2(ull& c, ull a, ull b) {
    asm("fma.rn.f32x2 %0, %1, %2, %0;" : "+l"(c) : "l"(a), "l"(b));
}
__device__ __forceinline__ float2 unpk(ull v) {
    float2 r; asm("mov.b64 {%0, %1}, %2;" : "=f"(r.x), "=f"(r.y) : "l"(v)); return r;
}

// ---------------- device scratch ---------------------------------------------
__device__ float g_enc1[B_DIM*E_DIM];
__device__ float g_enc2[B_DIM*E_DIM];
__device__ float g_affa[B_DIM*E_DIM];
__device__ float g_affv[B_DIM*E_DIM];
__device__ float g_Xa  [E_DIM*E_DIM];
__device__ float g_Xv  [E_DIM*E_DIM];

// ---------------- prep GEMM: 32x64 tiles, C[256,256] = A[256,K] @ W[256,K]^T --
__device__ __forceinline__ void small_gemm(const float* __restrict__ A,
                                           const float* __restrict__ W,
                                           const float* __restrict__ bias,
                                           float* __restrict__ C, int K)
{
    __shared__ float As[32][17];
    __shared__ float Ws[64][17];
    const int i0 = blockIdx.x * 32, j0 = blockIdx.y * 64;
    const int tid = threadIdx.x;
    const int tx = tid & 15, ty = tid >> 4;
    const int ar = tid >> 2, ak = (tid & 3) * 4;
    float acc[2][4] = {};
    for (int k0 = 0; k0 < K; k0 += 16) {
        float4 av = make_float4(0.f,0.f,0.f,0.f);
        if (tid < 128) av = *(const float4*)(A + (size_t)(i0 + ar) * K + k0 + ak);
        float4 wv = *(const float4*)(W + (size_t)(j0 + ar) * K + k0 + ak);
        __syncthreads();
        if (tid < 128) {
            As[ar][ak] = av.x; As[ar][ak+1] = av.y; As[ar][ak+2] = av.z; As[ar][ak+3] = av.w;
        }
        Ws[ar][ak] = wv.x; Ws[ar][ak+1] = wv.y; Ws[ar][ak+2] = wv.z; Ws[ar][ak+3] = wv.w;
        __syncthreads();
        #pragma unroll
        for (int kk = 0; kk < 16; kk++) {
            float a0 = As[ty*2][kk], a1 = As[ty*2+1][kk];
            float b0 = Ws[tx*4][kk], b1 = Ws[tx*4+1][kk];
            float b2 = Ws[tx*4+2][kk], b3 = Ws[tx*4+3][kk];
            acc[0][0] = fmaf(a0,b0,acc[0][0]); acc[0][1] = fmaf(a0,b1,acc[0][1]);
            acc[0][2] = fmaf(a0,b2,acc[0][2]); acc[0][3] = fmaf(a0,b3,acc[0][3]);
            acc[1][0] = fmaf(a1,b0,acc[1][0]); acc[1][1] = fmaf(a1,b1,acc[1][1]);
            acc[1][2] = fmaf(a1,b2,acc[1][2]); acc[1][3] = fmaf(a1,b3,acc[1][3]);
        }
    }
    #pragma unroll
    for (int u = 0; u < 2; u++)
        #pragma unroll
        for (int v = 0; v < 4; v++) {
            int j = j0 + tx*4 + v;
            float x = acc[u][v];
            if (bias) x += bias[j];
            C[(size_t)(i0 + ty*2 + u) * E_DIM + j] = x;
        }
}

__global__ void pre_enc_kernel(const float* __restrict__ f1, const float* __restrict__ f2,
                               const float* __restrict__ w1, const float* __restrict__ b1,
                               const float* __restrict__ w2, const float* __restrict__ b2)
{
    if (blockIdx.z == 0) small_gemm(f1, w1, b1, g_enc1, F_DIM);
    else                 small_gemm(f2, w2, b2, g_enc2, F_DIM);
}

__global__ void pre_aff_kernel(const float* __restrict__ affa, const float* __restrict__ affv,
                               const float* __restrict__ wa,   const float* __restrict__ wv)
{
    int z = blockIdx.z;
    const float* A = (z == 0 || z == 2) ? g_enc1 : g_enc2;
    const float* W = (z == 0) ? affa : (z == 1) ? affv : (z == 2) ? wa : wv;
    float*       C = (z == 0) ? g_affa : (z == 1) ? g_affv : (z == 2) ? g_Xa : g_Xv;
    small_gemm(A, W, nullptr, C, E_DIM);
}

// ---------------- main fused kernel ------------------------------------------
// acc2[rr][c] holds output columns (tn*8 + 2c, tn*8 + 2c + 1) packed fp32x2.
__device__ __forceinline__ void gemm_main(const float* __restrict__ Wg, int ldw,
                                          const float* As, float* Bs,
                                          ull acc2[8][4],
                                          int tm, int tn, int lj, int lk)
{
    float4 pre[4];
    #pragma unroll
    for (int r = 0; r < 4; r++)
        pre[r] = *(const float4*)(Wg + (size_t)(lj + 64*r) * ldw + lk);

    for (int k0 = 0; k0 < E_DIM; k0 += 16) {
        __syncthreads();
        #pragma unroll
        for (int r = 0; r < 4; r++) {
            float* dst = Bs + lk * BSP + (lj + 64*r);
            dst[0]     = pre[r].x;
            dst[BSP]   = pre[r].y;
            dst[2*BSP] = pre[r].z;
            dst[3*BSP] = pre[r].w;
        }
        __syncthreads();
        if (k0 + 16 < E_DIM) {
            #pragma unroll
            for (int r = 0; r < 4; r++)
                pre[r] = *(const float4*)(Wg + (size_t)(lj + 64*r) * ldw + (k0 + 16) + lk);
        }
        #pragma unroll
        for (int kk = 0; kk < 16; kk += 4) {
            float4 a4[8];
            #pragma unroll
            for (int rr = 0; rr < 8; rr++)
                a4[rr] = *(const float4*)(As + (tm*8 + rr) * E_DIM + (k0 + kk));
            #pragma unroll
            for (int q = 0; q < 4; q++) {
                ulonglong2 b0 = *(const ulonglong2*)(Bs + (kk + q) * BSP + tn*8);
                ulonglong2 b1 = *(const ulonglong2*)(Bs + (kk + q) * BSP + tn*8 + 4);
                #pragma unroll
                for (int rr = 0; rr < 8; rr++) {
                    float av = ((const float*)&a4[rr])[q];
                    ull ad = dup2(av);
                    ffma2(acc2[rr][0], ad, b0.x);
                    ffma2(acc2[rr][1], ad, b0.y);
                    ffma2(acc2[rr][2], ad, b1.x);
                    ffma2(acc2[rr][3], ad, b1.y);
                }
            }
        }
    }
}

__device__ __forceinline__ void zero_acc(ull acc2[8][4]) {
    #pragma unroll
    for (int r = 0; r < 8; r++)
        #pragma unroll
        for (int c = 0; c < 4; c++) acc2[r][c] = 0ull;
}
__device__ __forceinline__ void unpack_row(const ull a2[4], float av[8]) {
    #pragma unroll
    for (int c = 0; c < 4; c++) {
        float2 t = unpk(a2[c]);
        av[2*c] = t.x; av[2*c+1] = t.y;
    }
}

__global__ void __launch_bounds__(256, 1)
fused_kernel(const float* __restrict__ wca, const float* __restrict__ wcv,
             const float* __restrict__ wha, const float* __restrict__ whv,
             const float* __restrict__ fc1w, const float* __restrict__ fc1b,
             const float* __restrict__ fc2w, const float* __restrict__ fc2b,
             float* __restrict__ out)
{
    extern __shared__ float sm[];
    float* A_buf = sm;
    float* O_buf = A_buf + TI*E_DIM;
    float* h_buf = O_buf + TI*E_DIM;
    float* Bs    = h_buf + TI*E_DIM;
    float* af    = Bs + 16*BSP;
    float* e1s   = af + E_DIM;

    const int tid = threadIdx.x;
    const int b   = blockIdx.y;
    const int i0  = blockIdx.x * TI;
    const int tm  = tid >> 5, tn = tid & 31;
    const int lj  = tid >> 2, lk = (tid & 3) * 4;

    for (int br = 0; br < 2; br++) {
        const float* genc = br ? g_enc2 : g_enc1;
        const float* gaff = br ? g_affv : g_affa;
        const float* gX   = br ? g_Xv   : g_Xa;
        const float* Wc   = br ? wcv : wca;
        const float* Wh   = br ? whv : wha;

        __syncthreads();
        af[tid] = gaff[b * E_DIM + tid];
        if (tid < TI) e1s[tid] = genc[b * E_DIM + i0 + tid];
        __syncthreads();

        {   // attn tile: A_buf[i][k] = tanh(enc[b,i0+i]*aff[b,k]/16)
            int gi = tid >> 2;
            int kb = (tid & 3) * 4;
            float ei = e1s[gi] * ATT_SCALE;
            for (int rep = 0; rep < 16; rep++) {
                int k = kb + rep * 16;
                float4 v;
                v.x = tanhf(ei * af[k]);
                v.y = tanhf(ei * af[k+1]);
                v.z = tanhf(ei * af[k+2]);
                v.w = tanhf(ei * af[k+3]);
                *(float4*)(A_buf + gi * E_DIM + k) = v;
            }
        }
        __syncthreads();

        ull acc2[8][4];

        // ---- GEMM1: O = relu(attn @ Wc^T + X) ----
        zero_acc(acc2);
        gemm_main(Wc, E_DIM, A_buf, Bs, acc2, tm, tn, lj, lk);
        #pragma unroll
        for (int rr = 0; rr < 8; rr++) {
            int r = tm*8 + rr;
            float av[8]; unpack_row(acc2[rr], av);
            const float* xr = gX + (size_t)(i0 + r) * E_DIM + tn*8;
            float4 x0 = *(const float4*)xr;
            float4 x1 = *(const float4*)(xr + 4);
            float4 o0, o1;
            o0.x = fmaxf(av[0] + x0.x, 0.f); o0.y = fmaxf(av[1] + x0.y, 0.f);
            o0.z = fmaxf(av[2] + x0.z, 0.f); o0.w = fmaxf(av[3] + x0.w, 0.f);
            o1.x = fmaxf(av[4] + x1.x, 0.f); o1.y = fmaxf(av[5] + x1.y, 0.f);
            o1.z = fmaxf(av[6] + x1.z, 0.f); o1.w = fmaxf(av[7] + x1.w, 0.f);
            *(float4*)(O_buf + r * E_DIM + tn*8)     = o0;
            *(float4*)(O_buf + r * E_DIM + tn*8 + 4) = o1;
        }
        __syncthreads();

        // ---- GEMM2: A_buf = O @ Wh^T + enc ----
        zero_acc(acc2);
        gemm_main(Wh, E_DIM, O_buf, Bs, acc2, tm, tn, lj, lk);
        #pragma unroll
        for (int rr = 0; rr < 8; rr++) {
            int r = tm*8 + rr;
            float av[8]; unpack_row(acc2[rr], av);
            const float* er = genc + (size_t)(i0 + r) * E_DIM + tn*8;
            float4 x0 = *(const float4*)er;
            float4 x1 = *(const float4*)(er + 4);
            float4 o0, o1;
            o0.x = av[0] + x0.x; o0.y = av[1] + x0.y;
            o0.z = av[2] + x0.z; o0.w = av[3] + x0.w;
            o1.x = av[4] + x1.x; o1.y = av[5] + x1.y;
            o1.z = av[6] + x1.z; o1.w = av[7] + x1.w;
            *(float4*)(A_buf + r * E_DIM + tn*8)     = o0;
            *(float4*)(A_buf + r * E_DIM + tn*8 + 4) = o1;
        }
        __syncthreads();

        // ---- GEMM3: h partial = attn_enc @ fc1_half^T ----
        zero_acc(acc2);
        gemm_main(fc1w + br * E_DIM, 2*E_DIM, A_buf, Bs, acc2, tm, tn, lj, lk);

        if (br == 0) {
            #pragma unroll
            for (int rr = 0; rr < 8; rr++) {
                int r = tm*8 + rr;
                float av[8]; unpack_row(acc2[rr], av);
                *(float4*)(h_buf + r * E_DIM + tn*8)     = make_float4(av[0],av[1],av[2],av[3]);
                *(float4*)(h_buf + r * E_DIM + tn*8 + 4) = make_float4(av[4],av[5],av[6],av[7]);
            }
        } else {
            float4 b0 = *(const float4*)(fc1b + tn*8);
            float4 b1 = *(const float4*)(fc1b + tn*8 + 4);
            float4 w0 = *(const float4*)(fc2w + tn*8);
            float4 w1 = *(const float4*)(fc2w + tn*8 + 4);
            float f2b = fc2b[0];
            #pragma unroll
            for (int rr = 0; rr < 8; rr++) {
                int r = tm*8 + rr;
                float av[8]; unpack_row(acc2[rr], av);
                float4 h0 = *(const float4*)(h_buf + r * E_DIM + tn*8);
                float4 h1 = *(const float4*)(h_buf + r * E_DIM + tn*8 + 4);
                float ps = 0.f;
                ps += fmaxf(av[0] + h0.x + b0.x, 0.f) * w0.x;
                ps += fmaxf(av[1] + h0.y + b0.y, 0.f) * w0.y;
                ps += fmaxf(av[2] + h0.z + b0.z, 0.f) * w0.z;
                ps += fmaxf(av[3] + h0.w + b0.w, 0.f) * w0.w;
                ps += fmaxf(av[4] + h1.x + b1.x, 0.f) * w1.x;
                ps += fmaxf(av[5] + h1.y + b1.y, 0.f) * w1.y;
                ps += fmaxf(av[6] + h1.z + b1.z, 0.f) * w1.z;
                ps += fmaxf(av[7] + h1.w + b1.w, 0.f) * w1.w;
                #pragma unroll
                for (int off = 16; off > 0; off >>= 1)
                    ps += __shfl_xor_sync(0xffffffffu, ps, off);
                if (tn == 0)
                    out[b * E_DIM + i0 + r] = ps + f2b;
            }
        }
    }
}

// ---------------- launch -----------------------------------------------------
extern "C" void kernel_launch(void* const* d_in, const int* in_sizes, int n_in,
                              void* d_out, int out_size)
{
    (void)in_sizes; (void)n_in; (void)out_size;
    const float* f1     = (const float*)d_in[0];
    const float* f2     = (const float*)d_in[1];
    const float* enc1_w = (const float*)d_in[2];
    const float* enc1_b = (const float*)d_in[3];
    const float* enc2_w = (const float*)d_in[4];
    const float* enc2_b = (const float*)d_in[5];
    const float* affa_w = (const float*)d_in[6];
    const float* affv_w = (const float*)d_in[7];
    const float* wa_w   = (const float*)d_in[8];
    const float* wv_w   = (const float*)d_in[9];
    const float* wca_w  = (const float*)d_in[10];
    const float* wcv_w  = (const float*)d_in[11];
    const float* wha_w  = (const float*)d_in[12];
    const float* whv_w  = (const float*)d_in[13];
    const float* fc1_w  = (const float*)d_in[14];
    const float* fc1_b  = (const float*)d_in[15];
    const float* fc2_w  = (const float*)d_in[16];
    const float* fc2_b  = (const float*)d_in[17];
    float* out = (float*)d_out;

    cudaFuncSetAttribute(fused_kernel,
                         cudaFuncAttributeMaxDynamicSharedMemorySize, SMEM_BYTES);

    pre_enc_kernel<<<dim3(8,4,2), 256>>>(f1, f2, enc1_w, enc1_b, enc2_w, enc2_b);
    pre_aff_kernel<<<dim3(8,4,4), 256>>>(affa_w, affv_w, wa_w, wv_w);
    fused_kernel<<<dim3(4, B_DIM), 256, SMEM_BYTES>>>(wca_w, wcv_w, wha_w, whv_w,
                                                      fc1_w, fc1_b, fc2_w, fc2_b, out);
}

// round 7
// speedup vs baseline: 1.9781x; 1.9781x over previous
#include <cuda_runtime.h>
#include <cuda_bf16.h>
#include <cstdint>
#include <math.h>

#define ATT_SCALE 0.0625f
typedef uint32_t u32;

// ---------------- SMEM byte offsets ------------------------------------------
#define WCHUNK  24576              // one staged W chunk: hi(12288) + lo(12288)
#define S_WBUF  0                  // 2 x WCHUNK (double buffer)
#define S_AHI   49152              // 64 x 264 bf16
#define S_ALO   82944
#define S_PARK  116736             // 64 x 260 fp32
#define S_AFF   183296             // 256 fp32
#define S_F1B   184320
#define S_F2W   185344
#define S_OSUM  186368             // 64 x 4 fp32
#define S_TOTAL 187392
#define A_STR   264                // bf16 per A row (pad: conflict-free ldmatrix)

// ---------------- device scratch ---------------------------------------------
__device__ float g_enc1[65536], g_enc2[65536];
__device__ float g_affa[65536], g_affv[65536];
__device__ float g_Xa[65536],   g_Xv[65536];
// 6 weights x 16 k-chunks x 24576 B (bf16 hi/lo, pre-padded staging layout)
__device__ uint4 g_wsp[6 * 16 * 1536];

// ---------------- small helpers ----------------------------------------------
__device__ __forceinline__ u32 smem_u32(const void* p) {
    u32 a;
    asm("{ .reg .u64 t; cvta.to.shared.u64 t, %1; cvt.u32.u64 %0, t; }" : "=r"(a) : "l"(p));
    return a;
}
__device__ __forceinline__ void ldsm4(u32 addr, u32* d) {
    asm volatile("ldmatrix.sync.aligned.m8n8.x4.shared.b16 {%0,%1,%2,%3}, [%4];"
        : "=r"(d[0]), "=r"(d[1]), "=r"(d[2]), "=r"(d[3]) : "r"(addr));
}
__device__ __forceinline__ void mma_bf16(float* c, const u32* a, const u32* b) {
    asm volatile("mma.sync.aligned.m16n8k16.row.col.f32.bf16.bf16.f32 "
        "{%0,%1,%2,%3}, {%4,%5,%6,%7}, {%8,%9}, {%0,%1,%2,%3};"
        : "+f"(c[0]), "+f"(c[1]), "+f"(c[2]), "+f"(c[3])
        : "r"(a[0]), "r"(a[1]), "r"(a[2]), "r"(a[3]), "r"(b[0]), "r"(b[1]));
}
__device__ __forceinline__ void split2(float v0, float v1, u32& rh, u32& rl) {
    __nv_bfloat16 h0 = __float2bfloat16(v0), h1 = __float2bfloat16(v1);
    __nv_bfloat16 l0 = __float2bfloat16(v0 - __bfloat162float(h0));
    __nv_bfloat16 l1 = __float2bfloat16(v1 - __bfloat162float(h1));
    rh = (u32)__bfloat16_as_ushort(h0) | ((u32)__bfloat16_as_ushort(h1) << 16);
    rl = (u32)__bfloat16_as_ushort(l0) | ((u32)__bfloat16_as_ushort(l1) << 16);
}
__device__ __forceinline__ float ftanh(float x) {
    float t = __expf(fminf(2.0f * x, 80.0f));
    return __fdividef(t - 1.0f, t + 1.0f);
}

// ---------------- prep GEMMs (SIMT fp32, known-correct since R5) --------------
__device__ __forceinline__ void small_gemm(const float* __restrict__ A,
                                           const float* __restrict__ W,
                                           const float* __restrict__ bias,
                                           float* __restrict__ C, int K)
{
    __shared__ float As[32][17];
    __shared__ float Ws[64][17];
    const int i0 = blockIdx.x * 32, j0 = blockIdx.y * 64;
    const int tid = threadIdx.x;
    const int tx = tid & 15, ty = tid >> 4;
    const int ar = tid >> 2, ak = (tid & 3) * 4;
    float acc[2][4] = {};
    for (int k0 = 0; k0 < K; k0 += 16) {
        float4 av = make_float4(0.f, 0.f, 0.f, 0.f);
        if (tid < 128) av = *(const float4*)(A + (size_t)(i0 + ar) * K + k0 + ak);
        float4 wv = *(const float4*)(W + (size_t)(j0 + ar) * K + k0 + ak);
        __syncthreads();
        if (tid < 128) {
            As[ar][ak] = av.x; As[ar][ak+1] = av.y; As[ar][ak+2] = av.z; As[ar][ak+3] = av.w;
        }
        Ws[ar][ak] = wv.x; Ws[ar][ak+1] = wv.y; Ws[ar][ak+2] = wv.z; Ws[ar][ak+3] = wv.w;
        __syncthreads();
        #pragma unroll
        for (int kk = 0; kk < 16; kk++) {
            float a0 = As[ty*2][kk], a1 = As[ty*2+1][kk];
            float b0 = Ws[tx*4][kk], b1 = Ws[tx*4+1][kk];
            float b2 = Ws[tx*4+2][kk], b3 = Ws[tx*4+3][kk];
            acc[0][0] = fmaf(a0,b0,acc[0][0]); acc[0][1] = fmaf(a0,b1,acc[0][1]);
            acc[0][2] = fmaf(a0,b2,acc[0][2]); acc[0][3] = fmaf(a0,b3,acc[0][3]);
            acc[1][0] = fmaf(a1,b0,acc[1][0]); acc[1][1] = fmaf(a1,b1,acc[1][1]);
            acc[1][2] = fmaf(a1,b2,acc[1][2]); acc[1][3] = fmaf(a1,b3,acc[1][3]);
        }
    }
    #pragma unroll
    for (int u = 0; u < 2; u++)
        #pragma unroll
        for (int v = 0; v < 4; v++) {
            int j = j0 + tx*4 + v;
            float x = acc[u][v];
            if (bias) x += bias[j];
            C[(size_t)(i0 + ty*2 + u) * 256 + j] = x;
        }
}

__global__ void pre_enc_kernel(const float* __restrict__ f1, const float* __restrict__ f2,
                               const float* __restrict__ w1, const float* __restrict__ b1,
                               const float* __restrict__ w2, const float* __restrict__ b2)
{
    if (blockIdx.z == 0) small_gemm(f1, w1, b1, g_enc1, 768);
    else                 small_gemm(f2, w2, b2, g_enc2, 768);
}

__global__ void pre_aff_kernel(const float* __restrict__ affa, const float* __restrict__ affv,
                               const float* __restrict__ wa,   const float* __restrict__ wv)
{
    int z = blockIdx.z;
    const float* A = (z == 0 || z == 2) ? g_enc1 : g_enc2;
    const float* W = (z == 0) ? affa : (z == 1) ? affv : (z == 2) ? wa : wv;
    float*       C = (z == 0) ? g_affa : (z == 1) ? g_affv : (z == 2) ? g_Xa : g_Xv;
    small_gemm(A, W, nullptr, C, 256);
}

// ---------------- weight split: fp32 -> bf16 hi/lo staging image --------------
// Layout per (weight w, k-chunk c): hi[j=0..255][24 bf16 row, 16 used] then lo.
__global__ void split_kernel(const float* __restrict__ wca, const float* __restrict__ wcv,
                             const float* __restrict__ wha, const float* __restrict__ whv,
                             const float* __restrict__ fc1w)
{
    int w = blockIdx.x, c = blockIdx.y, j = threadIdx.x;
    const float* src; int stride = 256, co = 0;
    switch (w) {
        case 0: src = wca; break;
        case 1: src = wha; break;
        case 2: src = fc1w; stride = 512; break;
        case 3: src = wcv; break;
        case 4: src = whv; break;
        default: src = fc1w; stride = 512; co = 256; break;
    }
    const float* rp = src + (size_t)j * stride + co + c * 16;
    uint8_t* dst = (uint8_t*)g_wsp + (size_t)(w * 16 + c) * WCHUNK;
    #pragma unroll
    for (int p = 0; p < 8; p++) {
        float f0 = rp[2*p], f1 = rp[2*p + 1];
        u32 rh, rl; split2(f0, f1, rh, rl);
        *(u32*)(dst + j*48 + p*4)         = rh;
        *(u32*)(dst + 12288 + j*48 + p*4) = rl;
    }
}

// ---------------- tensor-core mainloop ---------------------------------------
// acc[mt][nt][*] over C rows [r0+mt*16, +16), cols [c0+nt*8, +8).
__device__ __forceinline__ void run_gemm(const uint4* __restrict__ wsrc, char* sm, u32 sb,
                                         int tid, int lane, int r0, int c0,
                                         float acc[2][8][4])
{
    #pragma unroll
    for (int mt = 0; mt < 2; mt++)
        #pragma unroll
        for (int nt = 0; nt < 8; nt++)
            #pragma unroll
            for (int q = 0; q < 4; q++) acc[mt][nt][q] = 0.f;

    const int g = lane >> 3, r = lane & 7;
    // preload chunk 0
    #pragma unroll
    for (int q = 0; q < 6; q++)
        ((uint4*)(sm + S_WBUF))[q*256 + tid] = wsrc[q*256 + tid];
    __syncthreads();

    for (int c = 0; c < 16; c++) {
        uint4 pv[6];
        if (c < 15) {
            #pragma unroll
            for (int q = 0; q < 6; q++) pv[q] = wsrc[(c+1)*1536 + q*256 + tid];
        }
        u32 bufb = sb + S_WBUF + (u32)(c & 1) * WCHUNK;

        u32 ah[2][4], al[2][4];
        int arow = r0 + (g & 1)*8 + r;
        int akof = c*16 + (g >> 1)*8;
        #pragma unroll
        for (int mt = 0; mt < 2; mt++) {
            u32 ao = sb + S_AHI + (u32)(((arow + mt*16) * A_STR + akof) * 2);
            ldsm4(ao, ah[mt]);
            ldsm4(ao + (S_ALO - S_AHI), al[mt]);
        }

        u32 bh[8][2], bl[8][2];
        int jo = c0 + (g >> 1)*8 + r;
        int ko = (g & 1)*8;
        #pragma unroll
        for (int np = 0; np < 4; np++) {
            u32 bo = bufb + (u32)((jo + np*16) * 48 + ko * 2);
            u32 t[4];
            ldsm4(bo, t);
            bh[np*2][0] = t[0]; bh[np*2][1] = t[1]; bh[np*2+1][0] = t[2]; bh[np*2+1][1] = t[3];
            ldsm4(bo + 12288, t);
            bl[np*2][0] = t[0]; bl[np*2][1] = t[1]; bl[np*2+1][0] = t[2]; bl[np*2+1][1] = t[3];
        }

        #pragma unroll
        for (int mt = 0; mt < 2; mt++)
            #pragma unroll
            for (int nt = 0; nt < 8; nt++) {
                mma_bf16(acc[mt][nt], ah[mt], bh[nt]);
                mma_bf16(acc[mt][nt], al[mt], bh[nt]);
                mma_bf16(acc[mt][nt], ah[mt], bl[nt]);
            }

        if (c < 15) {
            char* db = sm + S_WBUF + ((c+1) & 1) * WCHUNK;
            #pragma unroll
            for (int q = 0; q < 6; q++) ((uint4*)db)[q*256 + tid] = pv[q];
        }
        __syncthreads();
    }
}

// ---------------- fused kernel -----------------------------------------------
__global__ void __launch_bounds__(256, 1)
mma_fused(const float* __restrict__ fc1b, const float* __restrict__ fc2w,
          const float* __restrict__ fc2b, float* __restrict__ out)
{
    extern __shared__ char sm[];
    u32 sb = smem_u32(sm);
    const int tid = threadIdx.x, lane = tid & 31, w = tid >> 5;
    const int b = blockIdx.y, i0 = blockIdx.x * 64;
    const int r0 = (w & 1) * 32, c0 = (w >> 1) * 64;
    const int qr = lane >> 2, qc = (lane & 3) * 2;

    ((float*)(sm + S_F1B))[tid] = fc1b[tid];
    ((float*)(sm + S_F2W))[tid] = fc2w[tid];

    float acc[2][8][4];

    for (int br = 0; br < 2; br++) {
        const float* genc = br ? g_enc2 : g_enc1;
        const float* gaff = br ? g_affv : g_affa;
        const float* gX   = br ? g_Xv   : g_Xa;
        const uint4* wb   = g_wsp + (size_t)(br * 3) * 16 * 1536;

        __syncthreads();
        ((float*)(sm + S_AFF))[tid] = gaff[b*256 + tid];
        __syncthreads();

        // ---- attn tile -> A hi/lo (rank-1 outer product, never hits GMEM) ----
        {
            int row = tid >> 2, cb = (tid & 3) * 64;
            float ev = genc[b*256 + i0 + row] * ATT_SCALE;
            const float* aff = (const float*)(sm + S_AFF);
            #pragma unroll 4
            for (int p = 0; p < 32; p++) {
                int col = cb + 2*p;
                float v0 = ftanh(ev * aff[col]), v1 = ftanh(ev * aff[col + 1]);
                u32 rh, rl; split2(v0, v1, rh, rl);
                u32 off = (u32)((row * A_STR + col) * 2);
                *(u32*)(sm + S_AHI + off) = rh;
                *(u32*)(sm + S_ALO + off) = rl;
            }
        }
        __syncthreads();

        // ---- GEMM1: D = attn @ Wc^T ; A = relu(D + X) ----
        run_gemm(wb, sm, sb, tid, lane, r0, c0, acc);
        #pragma unroll
        for (int mt = 0; mt < 2; mt++)
            #pragma unroll
            for (int rs = 0; rs < 2; rs++) {
                int row = r0 + mt*16 + rs*8 + qr;
                #pragma unroll
                for (int nt = 0; nt < 8; nt++) {
                    int col = c0 + nt*8 + qc;
                    float2 xv = *(const float2*)(gX + (size_t)(i0 + row)*256 + col);
                    float v0 = fmaxf(acc[mt][nt][rs*2]   + xv.x, 0.f);
                    float v1 = fmaxf(acc[mt][nt][rs*2+1] + xv.y, 0.f);
                    u32 rh, rl; split2(v0, v1, rh, rl);
                    u32 off = (u32)((row * A_STR + col) * 2);
                    *(u32*)(sm + S_AHI + off) = rh;
                    *(u32*)(sm + S_ALO + off) = rl;
                }
            }
        __syncthreads();

        // ---- GEMM2: D = H @ Wh^T ; A = D + enc ----
        run_gemm(wb + 16*1536, sm, sb, tid, lane, r0, c0, acc);
        #pragma unroll
        for (int mt = 0; mt < 2; mt++)
            #pragma unroll
            for (int rs = 0; rs < 2; rs++) {
                int row = r0 + mt*16 + rs*8 + qr;
                #pragma unroll
                for (int nt = 0; nt < 8; nt++) {
                    int col = c0 + nt*8 + qc;
                    float2 ev2 = *(const float2*)(genc + (size_t)(i0 + row)*256 + col);
                    float v0 = acc[mt][nt][rs*2]   + ev2.x;
                    float v1 = acc[mt][nt][rs*2+1] + ev2.y;
                    u32 rh, rl; split2(v0, v1, rh, rl);
                    u32 off = (u32)((row * A_STR + col) * 2);
                    *(u32*)(sm + S_AHI + off) = rh;
                    *(u32*)(sm + S_ALO + off) = rl;
                }
            }
        __syncthreads();

        // ---- GEMM3: D = attn_enc @ fc1_half^T ----
        run_gemm(wb + 32*1536, sm, sb, tid, lane, r0, c0, acc);
        if (br == 0) {
            #pragma unroll
            for (int mt = 0; mt < 2; mt++)
                #pragma unroll
                for (int rs = 0; rs < 2; rs++) {
                    int row = r0 + mt*16 + rs*8 + qr;
                    #pragma unroll
                    for (int nt = 0; nt < 8; nt++) {
                        int col = c0 + nt*8 + qc;
                        *(float2*)(sm + S_PARK + (u32)((row*260 + col) * 4)) =
                            make_float2(acc[mt][nt][rs*2], acc[mt][nt][rs*2+1]);
                    }
                }
        } else {
            const float* f1bs = (const float*)(sm + S_F1B);
            const float* f2ws = (const float*)(sm + S_F2W);
            #pragma unroll
            for (int mt = 0; mt < 2; mt++)
                #pragma unroll
                for (int rs = 0; rs < 2; rs++) {
                    int row = r0 + mt*16 + rs*8 + qr;
                    float s = 0.f;
                    #pragma unroll
                    for (int nt = 0; nt < 8; nt++) {
                        int col = c0 + nt*8 + qc;
                        float2 pk = *(const float2*)(sm + S_PARK + (u32)((row*260 + col) * 4));
                        float h0 = fmaxf(acc[mt][nt][rs*2]   + pk.x + f1bs[col],     0.f);
                        float h1 = fmaxf(acc[mt][nt][rs*2+1] + pk.y + f1bs[col + 1], 0.f);
                        s = fmaf(h0, f2ws[col], s);
                        s = fmaf(h1, f2ws[col + 1], s);
                    }
                    s += __shfl_xor_sync(0xffffffffu, s, 1);
                    s += __shfl_xor_sync(0xffffffffu, s, 2);
                    if ((lane & 3) == 0)
                        ((float*)(sm + S_OSUM))[row*4 + (w >> 1)] = s;
                }
            __syncthreads();
            if (tid < 64) {
                const float* os = (const float*)(sm + S_OSUM);
                out[b*256 + i0 + tid] =
                    os[tid*4] + os[tid*4+1] + os[tid*4+2] + os[tid*4+3] + fc2b[0];
            }
        }
        __syncthreads();
    }
}

// ---------------- launch -----------------------------------------------------
extern "C" void kernel_launch(void* const* d_in, const int* in_sizes, int n_in,
                              void* d_out, int out_size)
{
    (void)in_sizes; (void)n_in; (void)out_size;
    const float* f1     = (const float*)d_in[0];
    const float* f2     = (const float*)d_in[1];
    const float* enc1_w = (const float*)d_in[2];
    const float* enc1_b = (const float*)d_in[3];
    const float* enc2_w = (const float*)d_in[4];
    const float* enc2_b = (const float*)d_in[5];
    const float* affa_w = (const float*)d_in[6];
    const float* affv_w = (const float*)d_in[7];
    const float* wa_w   = (const float*)d_in[8];
    const float* wv_w   = (const float*)d_in[9];
    const float* wca_w  = (const float*)d_in[10];
    const float* wcv_w  = (const float*)d_in[11];
    const float* wha_w  = (const float*)d_in[12];
    const float* whv_w  = (const float*)d_in[13];
    const float* fc1_w  = (const float*)d_in[14];
    const float* fc1_b  = (const float*)d_in[15];
    const float* fc2_w  = (const float*)d_in[16];
    const float* fc2_b  = (const float*)d_in[17];
    float* out = (float*)d_out;

    cudaFuncSetAttribute(mma_fused, cudaFuncAttributeMaxDynamicSharedMemorySize, S_TOTAL);

    split_kernel<<<dim3(6, 16), 256>>>(wca_w, wcv_w, wha_w, whv_w, fc1_w);
    pre_enc_kernel<<<dim3(8, 4, 2), 256>>>(f1, f2, enc1_w, enc1_b, enc2_w, enc2_b);
    pre_aff_kernel<<<dim3(8, 4, 4), 256>>>(affa_w, affv_w, wa_w, wv_w);
    mma_fused<<<dim3(4, 256), 256, S_TOTAL>>>(fc1_b, fc2_w, fc2_b, out);
}